// round 15
// baseline (speedup 1.0000x reference)
#include <cuda_runtime.h>
#include <cuda_bf16.h>
#include <math.h>
#include <stdint.h>

#define B_   2
#define T_   2048
#define C_   768
#define H_   12
#define HS_  64
#define M_TOT (B_*T_)            // 4096
#define SCALE_F 0.03608439182435161f   // 1/sqrt(768)
// Q pre-scale with log2(e) folded in: softmax runs in exp2 domain.
#define QSCALE_F (0.03608439182435161f * 1.4426950408889634f)

// ---------------- scratch (device globals) ----------------------------------
__device__ __nv_bfloat16 g_xhi[M_TOT*C_], g_xlo[M_TOT*C_];
__device__ __nv_bfloat16 g_yhi[M_TOT*C_], g_ylo[M_TOT*C_];
__device__ __nv_bfloat16 g_uhi[M_TOT*C_], g_ulo[M_TOT*C_];  // scaled Q, [b,h,t,hs]
__device__ __nv_bfloat16 g_vhi[M_TOT*C_], g_vlo[M_TOT*C_];  // V, [b,h,t,hs]
__device__ __nv_bfloat16 g_wuhi[C_*C_], g_wulo[C_*C_];
__device__ __nv_bfloat16 g_wvhi[C_*C_], g_wvlo[C_*C_];
__device__ __nv_bfloat16 g_wphi[C_*C_], g_wplo[C_*C_];

// ---------------------------------------------------------------------------
__device__ __forceinline__ uint32_t smem_u32(const void* p) {
    uint32_t a;
    asm("{ .reg .u64 t; cvta.to.shared.u64 t, %1; cvt.u32.u64 %0, t; }"
        : "=r"(a) : "l"(p));
    return a;
}
__device__ __forceinline__ void ldsm_x4(uint32_t (&r)[4], uint32_t addr) {
    asm volatile("ldmatrix.sync.aligned.m8n8.x4.shared.b16 {%0,%1,%2,%3}, [%4];"
        : "=r"(r[0]), "=r"(r[1]), "=r"(r[2]), "=r"(r[3]) : "r"(addr));
}
__device__ __forceinline__ void ldsm_x2(uint32_t (&r)[2], uint32_t addr) {
    asm volatile("ldmatrix.sync.aligned.m8n8.x2.shared.b16 {%0,%1}, [%2];"
        : "=r"(r[0]), "=r"(r[1]) : "r"(addr));
}
__device__ __forceinline__ void ldsm_x4t(uint32_t (&r)[4], uint32_t addr) {
    asm volatile("ldmatrix.sync.aligned.m8n8.x4.trans.shared.b16 {%0,%1,%2,%3}, [%4];"
        : "=r"(r[0]), "=r"(r[1]), "=r"(r[2]), "=r"(r[3]) : "r"(addr));
}
__device__ __forceinline__ void mma16816(float (&d)[4], const uint32_t (&a)[4],
                                         uint32_t b0, uint32_t b1) {
    asm volatile(
        "mma.sync.aligned.m16n8k16.row.col.f32.bf16.bf16.f32 "
        "{%0,%1,%2,%3}, {%4,%5,%6,%7}, {%8,%9}, {%0,%1,%2,%3};"
        : "+f"(d[0]), "+f"(d[1]), "+f"(d[2]), "+f"(d[3])
        : "r"(a[0]), "r"(a[1]), "r"(a[2]), "r"(a[3]), "r"(b0), "r"(b1));
}
__device__ __forceinline__ void cp16(uint32_t dst, const void* src) {
    asm volatile("cp.async.cg.shared.global [%0], [%1], 16;"
                 :: "r"(dst), "l"(src));
}
#define CP_COMMIT() asm volatile("cp.async.commit_group;" ::: "memory")
#define CP_WAIT0()  asm volatile("cp.async.wait_group 0;" ::: "memory")
#define CP_WAIT1()  asm volatile("cp.async.wait_group 1;" ::: "memory")
#define CP_WAIT2()  asm volatile("cp.async.wait_group 2;" ::: "memory")

__device__ __forceinline__ float ex2f(float x) {
    float y;
    asm("ex2.approx.f32 %0, %1;" : "=f"(y) : "f"(x));
    return y;
}

// truncation-based split: hi = top 16 bits (1 PRMT), lo = exact residual
// rounded to bf16 (1 cvt). Dropped lo*lo term ~2^-16 relative.
__device__ __forceinline__ void split2(float f0, float f1, uint32_t& hi, uint32_t& lo) {
    uint32_t u0 = __float_as_uint(f0), u1 = __float_as_uint(f1);
    uint32_t h;
    asm("prmt.b32 %0, %1, %2, 0x7632;" : "=r"(h) : "r"(u0), "r"(u1));
    const float l0 = f0 - __uint_as_float(u0 & 0xffff0000u);
    const float l1 = f1 - __uint_as_float(u1 & 0xffff0000u);
    uint32_t lp;
    asm("cvt.rn.bf16x2.f32 %0, %1, %2;" : "=r"(lp) : "f"(l1), "f"(l0));
    hi = h; lo = lp;
}

// ---------------------------------------------------------------------------
// merged fp32 -> bf16 hi/lo split (grid-stride)
// ---------------------------------------------------------------------------
#define N4X ((M_TOT*C_)/4)
#define N4W ((C_*C_)/4)
#define NTOT4 (N4X + 3*N4W)

__global__ void split_all(const float* __restrict__ x, const float* __restrict__ wu,
                          const float* __restrict__ wv, const float* __restrict__ wp)
{
    for (int i = blockIdx.x * blockDim.x + threadIdx.x; i < NTOT4;
         i += gridDim.x * blockDim.x) {
        const float* src;
        __nv_bfloat16 *hi, *lo;
        int j;
        if (i < N4X)              { src = x;  hi = g_xhi;  lo = g_xlo;  j = i; }
        else if (i < N4X + N4W)   { src = wu; hi = g_wuhi; lo = g_wulo; j = i - N4X; }
        else if (i < N4X + 2*N4W) { src = wv; hi = g_wvhi; lo = g_wvlo; j = i - N4X - N4W; }
        else                      { src = wp; hi = g_wphi; lo = g_wplo; j = i - N4X - 2*N4W; }
        float4 v = reinterpret_cast<const float4*>(src)[j];
        uint32_t h0, l0, h1, l1;
        split2(v.x, v.y, h0, l0);
        split2(v.z, v.w, h1, l1);
        reinterpret_cast<uint32_t*>(hi)[j*2+0] = h0;
        reinterpret_cast<uint32_t*>(hi)[j*2+1] = h1;
        reinterpret_cast<uint32_t*>(lo)[j*2+0] = l0;
        reinterpret_cast<uint32_t*>(lo)[j*2+1] = l1;
    }
}

// ---------------------------------------------------------------------------
// Pipelined HMMA GEMM (R13/R14 config, unchanged). CTA 128x96, K-chunk 64,
// 2 stages, safe 1-ahead pipeline.
// ---------------------------------------------------------------------------
#define GEMM_STAGE   57344
#define GEMM_SMEM_BYTES (2*GEMM_STAGE)

__device__ __forceinline__ int sw128(int r, int c) {
    return r * 128 + ((c ^ (r & 7)) << 4);
}

template<int MODE>
__global__ __launch_bounds__(256, 2)
void gemm_pipe(const float* __restrict__ bias0, const float* __restrict__ bias1,
               float* __restrict__ outp)
{
    extern __shared__ char sm[];
    const uint32_t sb = smem_u32(sm);

    const int z = (MODE == 0) ? blockIdx.z : 0;
    const __nv_bfloat16* Ahi = (MODE == 1) ? g_yhi : g_xhi;
    const __nv_bfloat16* Alo = (MODE == 1) ? g_ylo : g_xlo;
    const __nv_bfloat16* Bhi = (MODE == 1) ? g_wphi : (z ? g_wvhi : g_wuhi);
    const __nv_bfloat16* Blo = (MODE == 1) ? g_wplo : (z ? g_wvlo : g_wulo);
    const float* bias = (MODE == 1) ? bias0 : (z ? bias1 : bias0);

    const int tid = threadIdx.x;
    const int wid = tid >> 5, lane = tid & 31;
    const int m0 = blockIdx.y * 128;
    const int n0 = blockIdx.x * 96;
    const int wm = (wid & 1) * 64;
    const int wn = (wid >> 1) * 24;

    float acc[4][3][4];
    #pragma unroll
    for (int a = 0; a < 4; a++)
        #pragma unroll
        for (int b = 0; b < 3; b++)
            #pragma unroll
            for (int c = 0; c < 4; c++) acc[a][b][c] = 0.f;

    const int lr = tid >> 3, lc = tid & 7;

    auto issue = [&](int kc, int st) {
        const uint32_t s = sb + st * GEMM_STAGE;
        const int kcol = kc * 64;
        #pragma unroll
        for (int it = 0; it < 4; it++) {
            const int r = lr + it * 32;
            const int off = sw128(r, lc);
            const size_t ga = (size_t)(m0 + r) * C_ + kcol + lc * 8;
            cp16(s + off,         Ahi + ga);
            cp16(s + 16384 + off, Alo + ga);
        }
        #pragma unroll
        for (int it = 0; it < 3; it++) {
            const int r = lr + it * 32;
            const int off = sw128(r, lc);
            const size_t gb = (size_t)(n0 + r) * C_ + kcol + lc * 8;
            cp16(s + 32768 + off, Bhi + gb);
            cp16(s + 45056 + off, Blo + gb);
        }
        CP_COMMIT();
    };

    const int a_r = lane & 15, a_co = lane >> 4;
    const int b_r = (lane & 7) + ((lane >> 4) << 3), b_co = (lane >> 3) & 1;
    const int b2_r = lane & 7, b2_co = (lane >> 3) & 1;

    issue(0, 0);
    for (int kc = 0; kc < 12; kc++) {
        CP_WAIT0();
        __syncthreads();
        if (kc + 1 < 12) issue(kc + 1, (kc + 1) & 1);
        const uint32_t s = sb + (kc & 1) * GEMM_STAGE;
        #pragma unroll
        for (int ks = 0; ks < 4; ks++) {
            uint32_t bhi[4], blo[4], bhi2[2], blo2[2];
            {
                const int row = wn + b_r;
                const uint32_t bad = s + 32768 + sw128(row, ks * 2 + b_co);
                ldsm_x4(bhi, bad);
                ldsm_x4(blo, bad + 12288);
                const int row2 = wn + 16 + b2_r;
                const uint32_t bad2 = s + 32768 + sw128(row2, ks * 2 + b2_co);
                ldsm_x2(bhi2, bad2);
                ldsm_x2(blo2, bad2 + 12288);
            }
            uint32_t ahi[4][4], alo[4][4];
            #pragma unroll
            for (int mt = 0; mt < 4; mt++) {
                const int arow = wm + mt * 16 + a_r;
                const uint32_t aad = s + sw128(arow, ks * 2 + a_co);
                ldsm_x4(ahi[mt], aad);
                ldsm_x4(alo[mt], aad + 16384);
            }
            #pragma unroll
            for (int mt = 0; mt < 4; mt++) {
                mma16816(acc[mt][0], ahi[mt], bhi[0], bhi[1]);
                mma16816(acc[mt][1], ahi[mt], bhi[2], bhi[3]);
                mma16816(acc[mt][2], ahi[mt], bhi2[0], bhi2[1]);
            }
            #pragma unroll
            for (int mt = 0; mt < 4; mt++) {
                mma16816(acc[mt][0], ahi[mt], blo[0], blo[1]);
                mma16816(acc[mt][1], ahi[mt], blo[2], blo[3]);
                mma16816(acc[mt][2], ahi[mt], blo2[0], blo2[1]);
            }
            #pragma unroll
            for (int mt = 0; mt < 4; mt++) {
                mma16816(acc[mt][0], alo[mt], bhi[0], bhi[1]);
                mma16816(acc[mt][1], alo[mt], bhi[2], bhi[3]);
                mma16816(acc[mt][2], alo[mt], bhi2[0], bhi2[1]);
            }
        }
        __syncthreads();
    }

    const int er = lane >> 2, ec = (lane & 3) * 2;
    #pragma unroll
    for (int mt = 0; mt < 4; mt++) {
        #pragma unroll
        for (int nt = 0; nt < 3; nt++) {
            const int n = n0 + wn + nt * 8 + ec;
            const float b0 = bias[n], b1 = bias[n + 1];
            #pragma unroll
            for (int half = 0; half < 2; half++) {
                const int m = m0 + wm + mt * 16 + er + half * 8;
                float v0 = acc[mt][nt][half * 2 + 0] + b0;
                float v1 = acc[mt][nt][half * 2 + 1] + b1;
                if (MODE == 1) {
                    *(float2*)(outp + (size_t)m * C_ + n) = make_float2(v0, v1);
                } else {
                    if (z == 0) { v0 *= QSCALE_F; v1 *= QSCALE_F; }
                    const int bb = m >> 11, t = m & (T_ - 1);
                    const int hh = n >> 6, hs = n & 63;
                    uint32_t hi, lo;
                    split2(v0, v1, hi, lo);
                    __nv_bfloat16* dhi = z ? g_vhi : g_uhi;
                    __nv_bfloat16* dlo = z ? g_vlo : g_ulo;
                    const size_t off = (((size_t)(bb * H_ + hh)) * T_ + t) * HS_ + hs;
                    *(uint32_t*)(dhi + off) = hi;
                    *(uint32_t*)(dlo + off) = lo;
                }
            }
        }
    }
}

// ---------------------------------------------------------------------------
// HMMA flash attention with S-LOOKAHEAD: S(kt+1) MMAs issued before softmax(kt)
// so softmax ALU overlaps tensor-pipe drain. 3 KV stages (64KB each), Q staged
// through stage 2 once then hoisted to registers. One barrier per tile.
// stage s @ sb + s*64K: Khi@0 Klo@16K Vhi@32K Vlo@48K
// ---------------------------------------------------------------------------
#define ATTN_STAGE 65536
#define ATTN_SMEM  (3*ATTN_STAGE)

__device__ __forceinline__ void compute_S(float (&s)[16][4], uint32_t s0,
        const uint32_t (&qfh)[4][4], const uint32_t (&qfl)[4][4],
        int b_r, int b_co)
{
    #pragma unroll
    for (int i = 0; i < 16; i++)
        #pragma unroll
        for (int j = 0; j < 4; j++) s[i][j] = 0.f;
    #pragma unroll
    for (int ks = 0; ks < 4; ks++) {
        #pragma unroll
        for (int btp = 0; btp < 4; btp++) {
            uint32_t kh[2][4], kl[2][4];
            #pragma unroll
            for (int e = 0; e < 2; e++) {
                const int row = (btp * 2 + e) * 16 + b_r;
                const uint32_t ad = s0 + row * 128 +
                                    (((ks * 2 + b_co) ^ (row & 7)) << 4);
                ldsm_x4(kh[e], ad);
                ldsm_x4(kl[e], ad + 16384);
            }
            #pragma unroll
            for (int e = 0; e < 2; e++)
                #pragma unroll
                for (int hf = 0; hf < 2; hf++)
                    mma16816(s[btp*4 + e*2 + hf], qfh[ks], kh[e][hf*2], kh[e][hf*2+1]);
            #pragma unroll
            for (int e = 0; e < 2; e++)
                #pragma unroll
                for (int hf = 0; hf < 2; hf++)
                    mma16816(s[btp*4 + e*2 + hf], qfh[ks], kl[e][hf*2], kl[e][hf*2+1]);
            #pragma unroll
            for (int e = 0; e < 2; e++)
                #pragma unroll
                for (int hf = 0; hf < 2; hf++)
                    mma16816(s[btp*4 + e*2 + hf], qfl[ks], kh[e][hf*2], kh[e][hf*2+1]);
        }
    }
}

template<typename F>
__device__ __forceinline__ void attn_iter(int kt, int qt, uint32_t sb,
        float (&sCur)[16][4], float (&sNxt)[16][4],
        const uint32_t (&qfh)[4][4], const uint32_t (&qfl)[4][4],
        float (&onn)[8][4], float& mi0, float& mi1, float& li0, float& li1,
        int b_r, int b_co, int wid, int lane, F&& issue_kv)
{
    CP_WAIT0();            // kv(kt+1) landed (kv(kt+2) not yet issued)
    __syncthreads();       // all warps past PV(kt-1); stage (kt+2)%3 free
    if (kt + 2 <= qt) issue_kv(kt + 2, (kt + 2) % 3);
    if (kt + 1 <= qt)
        compute_S(sNxt, sb + (uint32_t)((kt + 1) % 3) * ATTN_STAGE,
                  qfh, qfl, b_r, b_co);   // fills tensor pipe

    // ---- causal mask on current tile (diagonal only) ----
    if (kt == qt) {
        const int r0 = wid * 16 + (lane >> 2);
        #pragma unroll
        for (int nt = 0; nt < 16; nt++) {
            const int c = nt * 8 + 2 * (lane & 3);
            if (c     > r0)     sCur[nt][0] = -INFINITY;
            if (c + 1 > r0)     sCur[nt][1] = -INFINITY;
            if (c     > r0 + 8) sCur[nt][2] = -INFINITY;
            if (c + 1 > r0 + 8) sCur[nt][3] = -INFINITY;
        }
    }

    // ---- online softmax (exp2 domain) — overlaps with S(kt+1) MMA drain ----
    float mx0 = -INFINITY, mx1 = -INFINITY;
    #pragma unroll
    for (int nt = 0; nt < 16; nt++) {
        mx0 = fmaxf(mx0, fmaxf(sCur[nt][0], sCur[nt][1]));
        mx1 = fmaxf(mx1, fmaxf(sCur[nt][2], sCur[nt][3]));
    }
    mx0 = fmaxf(mx0, __shfl_xor_sync(0xffffffffu, mx0, 1));
    mx0 = fmaxf(mx0, __shfl_xor_sync(0xffffffffu, mx0, 2));
    mx1 = fmaxf(mx1, __shfl_xor_sync(0xffffffffu, mx1, 1));
    mx1 = fmaxf(mx1, __shfl_xor_sync(0xffffffffu, mx1, 2));
    const float mn0 = fmaxf(mi0, mx0), mn1 = fmaxf(mi1, mx1);
    const float al0 = ex2f(mi0 - mn0), al1 = ex2f(mi1 - mn1);
    mi0 = mn0; mi1 = mn1;
    float sum0 = 0.f, sum1 = 0.f;
    #pragma unroll
    for (int nt = 0; nt < 16; nt++) {
        sCur[nt][0] = ex2f(sCur[nt][0] - mn0);
        sCur[nt][1] = ex2f(sCur[nt][1] - mn0);
        sCur[nt][2] = ex2f(sCur[nt][2] - mn1);
        sCur[nt][3] = ex2f(sCur[nt][3] - mn1);
        sum0 += sCur[nt][0] + sCur[nt][1];
        sum1 += sCur[nt][2] + sCur[nt][3];
    }
    sum0 += __shfl_xor_sync(0xffffffffu, sum0, 1);
    sum0 += __shfl_xor_sync(0xffffffffu, sum0, 2);
    sum1 += __shfl_xor_sync(0xffffffffu, sum1, 1);
    sum1 += __shfl_xor_sync(0xffffffffu, sum1, 2);
    li0 = li0 * al0 + sum0;
    li1 = li1 * al1 + sum1;
    #pragma unroll
    for (int i = 0; i < 8; i++) {
        onn[i][0] *= al0; onn[i][1] *= al0;
        onn[i][2] *= al1; onn[i][3] *= al1;
    }

    // ---- O += P @ V (x4-trans V loads; term-grouped) ----
    const uint32_t s0v = sb + (uint32_t)(kt % 3) * ATTN_STAGE + 32768u;
    #pragma unroll
    for (int ks2 = 0; ks2 < 8; ks2++) {
        uint32_t ph[4], pl[4];
        split2(sCur[2*ks2][0],   sCur[2*ks2][1],   ph[0], pl[0]);
        split2(sCur[2*ks2][2],   sCur[2*ks2][3],   ph[1], pl[1]);
        split2(sCur[2*ks2+1][0], sCur[2*ks2+1][1], ph[2], pl[2]);
        split2(sCur[2*ks2+1][2], sCur[2*ks2+1][3], ph[3], pl[3]);
        const int krow = ks2 * 16 + (lane & 15);
        #pragma unroll
        for (int hb = 0; hb < 2; hb++) {
            uint32_t vh[2][4], vl[2][4];
            #pragma unroll
            for (int pp = 0; pp < 2; pp++) {
                const int nt2e = hb * 4 + pp * 2;
                const uint32_t ad = s0v + krow * 128 +
                                    (((nt2e + (lane >> 4)) ^ (krow & 7)) << 4);
                ldsm_x4t(vh[pp], ad);
                ldsm_x4t(vl[pp], ad + 16384);
            }
            #pragma unroll
            for (int q = 0; q < 4; q++)
                mma16816(onn[hb*4 + q], ph, vh[q>>1][(q&1)*2], vh[q>>1][(q&1)*2+1]);
            #pragma unroll
            for (int q = 0; q < 4; q++)
                mma16816(onn[hb*4 + q], ph, vl[q>>1][(q&1)*2], vl[q>>1][(q&1)*2+1]);
            #pragma unroll
            for (int q = 0; q < 4; q++)
                mma16816(onn[hb*4 + q], pl, vh[q>>1][(q&1)*2], vh[q>>1][(q&1)*2+1]);
        }
    }
}

__global__ __launch_bounds__(256, 1)
void attn_mma()
{
    extern __shared__ char sm[];
    const uint32_t sb = smem_u32(sm);
    const int tid = threadIdx.x, wid = tid >> 5, lane = tid & 31;
    const int qt = (int)(gridDim.x - 1) - (int)blockIdx.x;  // longest first
    const int bh = blockIdx.y;
    const int b = bh / H_, h = bh % H_;
    const int q0 = qt * 128;

    const __nv_bfloat16* Kh = g_xhi + (size_t)b * T_ * C_ + h * HS_;
    const __nv_bfloat16* Kl = g_xlo + (size_t)b * T_ * C_ + h * HS_;
    const __nv_bfloat16* Vh = g_vhi + (size_t)bh * T_ * HS_;
    const __nv_bfloat16* Vl = g_vlo + (size_t)bh * T_ * HS_;
    const __nv_bfloat16* Qh = g_uhi + (size_t)bh * T_ * HS_;
    const __nv_bfloat16* Ql = g_ulo + (size_t)bh * T_ * HS_;

    int ldr[4], ldo[4], ldc[4];
    #pragma unroll
    for (int it = 0; it < 4; it++) {
        int f = tid + it * 256;
        int r = f >> 3, ch = f & 7;
        ldr[it] = r; ldc[it] = ch;
        ldo[it] = r * 128 + ((ch ^ (r & 7)) << 4);
    }

    auto issue_kv = [&](int kt, int st) {
        const int k0 = kt * 128;
        const uint32_t s = sb + st * ATTN_STAGE;
        #pragma unroll
        for (int it = 0; it < 4; it++) {
            const size_t gk = (size_t)(k0 + ldr[it]) * C_ + ldc[it] * 8;
            const size_t gv = (size_t)(k0 + ldr[it]) * HS_ + ldc[it] * 8;
            cp16(s + ldo[it],         Kh + gk);
            cp16(s + 16384 + ldo[it], Kl + gk);
            cp16(s + 32768 + ldo[it], Vh + gv);
            cp16(s + 49152 + ldo[it], Vl + gv);
        }
        CP_COMMIT();
    };

    // prologue: Q -> stage 2 (group 1), kv(0) -> stage 0, kv(1) -> stage 1
    {
        const uint32_t qbase = sb + 2u * ATTN_STAGE;
        #pragma unroll
        for (int it = 0; it < 4; it++) {
            const size_t g = (size_t)(q0 + ldr[it]) * HS_ + ldc[it] * 8;
            cp16(qbase + ldo[it],         Qh + g);
            cp16(qbase + 16384 + ldo[it], Ql + g);
        }
        CP_COMMIT();
    }
    issue_kv(0, 0);
    issue_kv(1, 1);

    const int a_r = lane & 15, a_co = lane >> 4;
    const int b_r = (lane & 7) + ((lane >> 4) << 3), b_co = (lane >> 3) & 1;

    // hoist Q fragments (Q in stage 2; overwritten later by kv(2))
    uint32_t qfh[4][4], qfl[4][4];
    CP_WAIT2();
    __syncthreads();
    {
        const uint32_t qbase = sb + 2u * ATTN_STAGE;
        const int row = wid * 16 + a_r;
        #pragma unroll
        for (int ks = 0; ks < 4; ks++) {
            const uint32_t ad = qbase + row * 128 +
                                (((ks * 2 + a_co) ^ (row & 7)) << 4);
            ldsm_x4(qfh[ks], ad);
            ldsm_x4(qfl[ks], ad + 16384);
        }
    }

    float onn[8][4];
    #pragma unroll
    for (int i = 0; i < 8; i++)
        #pragma unroll
        for (int j = 0; j < 4; j++) onn[i][j] = 0.f;
    float mi0 = -INFINITY, mi1 = -INFINITY, li0 = 0.f, li1 = 0.f;

    // S(0) from stage 0
    float sA[16][4], sB[16][4];
    CP_WAIT1();
    __syncthreads();
    compute_S(sA, sb, qfh, qfl, b_r, b_co);

    for (int kt = 0; kt <= qt; kt += 2) {
        attn_iter(kt, qt, sb, sA, sB, qfh, qfl, onn, mi0, mi1, li0, li1,
                  b_r, b_co, wid, lane, issue_kv);
        if (kt + 1 <= qt)
            attn_iter(kt + 1, qt, sb, sB, sA, qfh, qfl, onn, mi0, mi1, li0, li1,
                      b_r, b_co, wid, lane, issue_kv);
    }

    // ---- epilogue: y as bf16 hi/lo ----
    const float inv0 = 1.f / li0, inv1 = 1.f / li1;
    const int r0g = q0 + wid * 16 + (lane >> 2);
    #pragma unroll
    for (int nt2 = 0; nt2 < 8; nt2++) {
        const int c = h * HS_ + nt2 * 8 + 2 * (lane & 3);
        uint32_t hi, lo;
        const size_t o0 = (size_t)(b * T_ + r0g) * C_ + c;
        split2(onn[nt2][0] * inv0, onn[nt2][1] * inv0, hi, lo);
        *(uint32_t*)(g_yhi + o0) = hi;
        *(uint32_t*)(g_ylo + o0) = lo;
        const size_t o1 = (size_t)(b * T_ + r0g + 8) * C_ + c;
        split2(onn[nt2][2] * inv1, onn[nt2][3] * inv1, hi, lo);
        *(uint32_t*)(g_yhi + o1) = hi;
        *(uint32_t*)(g_ylo + o1) = lo;
    }
}

// ---------------------------------------------------------------------------
extern "C" void kernel_launch(void* const* d_in, const int* in_sizes, int n_in,
                              void* d_out, int out_size)
{
    (void)in_sizes; (void)n_in; (void)out_size;
    const float* x      = (const float*)d_in[0];
    const float* w_u_w  = (const float*)d_in[1];
    const float* w_u_b  = (const float*)d_in[2];
    const float* w_v_w  = (const float*)d_in[3];
    const float* w_v_b  = (const float*)d_in[4];
    const float* proj_w = (const float*)d_in[5];
    const float* proj_b = (const float*)d_in[6];
    float* out = (float*)d_out;

    cudaFuncSetAttribute(gemm_pipe<0>,
                         cudaFuncAttributeMaxDynamicSharedMemorySize, GEMM_SMEM_BYTES);
    cudaFuncSetAttribute(gemm_pipe<1>,
                         cudaFuncAttributeMaxDynamicSharedMemorySize, GEMM_SMEM_BYTES);
    cudaFuncSetAttribute(attn_mma,
                         cudaFuncAttributeMaxDynamicSharedMemorySize, ATTN_SMEM);

    split_all<<<592, 256>>>(x, w_u_w, w_v_w, proj_w);

    gemm_pipe<0><<<dim3(8, 32, 2), 256, GEMM_SMEM_BYTES>>>(w_u_b, w_v_b, nullptr);

    attn_mma<<<dim3(T_/128, B_*H_), 256, ATTN_SMEM>>>();

    gemm_pipe<1><<<dim3(8, 32, 1), 256, GEMM_SMEM_BYTES>>>(proj_b, nullptr, out);
}

// round 16
// speedup vs baseline: 1.0323x; 1.0323x over previous
#include <cuda_runtime.h>
#include <cuda_bf16.h>
#include <math.h>
#include <stdint.h>

#define B_   2
#define T_   2048
#define C_   768
#define H_   12
#define HS_  64
#define M_TOT (B_*T_)            // 4096
#define SCALE_F 0.03608439182435161f   // 1/sqrt(768)
// Q pre-scale with log2(e) folded in: softmax runs in exp2 domain.
#define QSCALE_F (0.03608439182435161f * 1.4426950408889634f)

// ---------------- scratch (device globals) ----------------------------------
__device__ __nv_bfloat16 g_xhi[M_TOT*C_], g_xlo[M_TOT*C_];
__device__ __nv_bfloat16 g_yhi[M_TOT*C_], g_ylo[M_TOT*C_];
__device__ __nv_bfloat16 g_uhi[M_TOT*C_], g_ulo[M_TOT*C_];  // scaled Q, [b,h,t,hs]
__device__ __nv_bfloat16 g_vhi[M_TOT*C_], g_vlo[M_TOT*C_];  // V, [b,h,t,hs]
__device__ __nv_bfloat16 g_wuhi[C_*C_], g_wulo[C_*C_];
__device__ __nv_bfloat16 g_wvhi[C_*C_], g_wvlo[C_*C_];
__device__ __nv_bfloat16 g_wphi[C_*C_], g_wplo[C_*C_];

// ---------------------------------------------------------------------------
__device__ __forceinline__ uint32_t smem_u32(const void* p) {
    uint32_t a;
    asm("{ .reg .u64 t; cvta.to.shared.u64 t, %1; cvt.u32.u64 %0, t; }"
        : "=r"(a) : "l"(p));
    return a;
}
__device__ __forceinline__ void ldsm_x4(uint32_t (&r)[4], uint32_t addr) {
    asm volatile("ldmatrix.sync.aligned.m8n8.x4.shared.b16 {%0,%1,%2,%3}, [%4];"
        : "=r"(r[0]), "=r"(r[1]), "=r"(r[2]), "=r"(r[3]) : "r"(addr));
}
__device__ __forceinline__ void ldsm_x2(uint32_t (&r)[2], uint32_t addr) {
    asm volatile("ldmatrix.sync.aligned.m8n8.x2.shared.b16 {%0,%1}, [%2];"
        : "=r"(r[0]), "=r"(r[1]) : "r"(addr));
}
__device__ __forceinline__ void ldsm_x4t(uint32_t (&r)[4], uint32_t addr) {
    asm volatile("ldmatrix.sync.aligned.m8n8.x4.trans.shared.b16 {%0,%1,%2,%3}, [%4];"
        : "=r"(r[0]), "=r"(r[1]), "=r"(r[2]), "=r"(r[3]) : "r"(addr));
}
__device__ __forceinline__ void mma16816(float (&d)[4], const uint32_t (&a)[4],
                                         uint32_t b0, uint32_t b1) {
    asm volatile(
        "mma.sync.aligned.m16n8k16.row.col.f32.bf16.bf16.f32 "
        "{%0,%1,%2,%3}, {%4,%5,%6,%7}, {%8,%9}, {%0,%1,%2,%3};"
        : "+f"(d[0]), "+f"(d[1]), "+f"(d[2]), "+f"(d[3])
        : "r"(a[0]), "r"(a[1]), "r"(a[2]), "r"(a[3]), "r"(b0), "r"(b1));
}
__device__ __forceinline__ void cp16(uint32_t dst, const void* src) {
    asm volatile("cp.async.cg.shared.global [%0], [%1], 16;"
                 :: "r"(dst), "l"(src));
}
#define CP_COMMIT() asm volatile("cp.async.commit_group;" ::: "memory")
#define CP_WAIT0()  asm volatile("cp.async.wait_group 0;" ::: "memory")
#define CP_WAIT1()  asm volatile("cp.async.wait_group 1;" ::: "memory")

__device__ __forceinline__ float ex2f(float x) {
    float y;
    asm("ex2.approx.f32 %0, %1;" : "=f"(y) : "f"(x));
    return y;
}

// truncation-based split: hi = top 16 bits (1 PRMT), lo = exact residual
// rounded to bf16 (1 cvt). Dropped lo*lo term ~2^-16 relative.
__device__ __forceinline__ void split2(float f0, float f1, uint32_t& hi, uint32_t& lo) {
    uint32_t u0 = __float_as_uint(f0), u1 = __float_as_uint(f1);
    uint32_t h;
    asm("prmt.b32 %0, %1, %2, 0x7632;" : "=r"(h) : "r"(u0), "r"(u1));
    const float l0 = f0 - __uint_as_float(u0 & 0xffff0000u);
    const float l1 = f1 - __uint_as_float(u1 & 0xffff0000u);
    uint32_t lp;
    asm("cvt.rn.bf16x2.f32 %0, %1, %2;" : "=r"(lp) : "f"(l1), "f"(l0));
    hi = h; lo = lp;
}

// ---------------------------------------------------------------------------
// merged fp32 -> bf16 hi/lo split (grid-stride, one wave)
// ---------------------------------------------------------------------------
#define N4X ((M_TOT*C_)/4)
#define N4W ((C_*C_)/4)
#define NTOT4 (N4X + 3*N4W)

__global__ void split_all(const float* __restrict__ x, const float* __restrict__ wu,
                          const float* __restrict__ wv, const float* __restrict__ wp)
{
    for (int i = blockIdx.x * blockDim.x + threadIdx.x; i < NTOT4;
         i += gridDim.x * blockDim.x) {
        const float* src;
        __nv_bfloat16 *hi, *lo;
        int j;
        if (i < N4X)              { src = x;  hi = g_xhi;  lo = g_xlo;  j = i; }
        else if (i < N4X + N4W)   { src = wu; hi = g_wuhi; lo = g_wulo; j = i - N4X; }
        else if (i < N4X + 2*N4W) { src = wv; hi = g_wvhi; lo = g_wvlo; j = i - N4X - N4W; }
        else                      { src = wp; hi = g_wphi; lo = g_wplo; j = i - N4X - 2*N4W; }
        float4 v = reinterpret_cast<const float4*>(src)[j];
        uint32_t h0, l0, h1, l1;
        split2(v.x, v.y, h0, l0);
        split2(v.z, v.w, h1, l1);
        reinterpret_cast<uint32_t*>(hi)[j*2+0] = h0;
        reinterpret_cast<uint32_t*>(hi)[j*2+1] = h1;
        reinterpret_cast<uint32_t*>(lo)[j*2+0] = l0;
        reinterpret_cast<uint32_t*>(lo)[j*2+1] = l1;
    }
}

// ---------------------------------------------------------------------------
// Pipelined HMMA GEMM (R14 config). CTA 128x96, K-chunk 64, 2 stages,
// safe 1-ahead pipeline. stage (56KB): Ahi@0(16K) Alo@16K Bhi@32K(12K)
// Blo@45056; sw128.
// MODE 0: fused u/v (blockIdx.z), A = x;  MODE 1: proj, A = y -> fp32 out
// ---------------------------------------------------------------------------
#define GEMM_STAGE   57344
#define GEMM_SMEM_BYTES (2*GEMM_STAGE)

__device__ __forceinline__ int sw128(int r, int c) {
    return r * 128 + ((c ^ (r & 7)) << 4);
}

template<int MODE>
__global__ __launch_bounds__(256, 2)
void gemm_pipe(const float* __restrict__ bias0, const float* __restrict__ bias1,
               float* __restrict__ outp)
{
    extern __shared__ char sm[];
    const uint32_t sb = smem_u32(sm);

    const int z = (MODE == 0) ? blockIdx.z : 0;
    const __nv_bfloat16* Ahi = (MODE == 1) ? g_yhi : g_xhi;
    const __nv_bfloat16* Alo = (MODE == 1) ? g_ylo : g_xlo;
    const __nv_bfloat16* Bhi = (MODE == 1) ? g_wphi : (z ? g_wvhi : g_wuhi);
    const __nv_bfloat16* Blo = (MODE == 1) ? g_wplo : (z ? g_wvlo : g_wulo);
    const float* bias = (MODE == 1) ? bias0 : (z ? bias1 : bias0);

    const int tid = threadIdx.x;
    const int wid = tid >> 5, lane = tid & 31;
    const int m0 = blockIdx.y * 128;
    const int n0 = blockIdx.x * 96;
    const int wm = (wid & 1) * 64;
    const int wn = (wid >> 1) * 24;

    float acc[4][3][4];
    #pragma unroll
    for (int a = 0; a < 4; a++)
        #pragma unroll
        for (int b = 0; b < 3; b++)
            #pragma unroll
            for (int c = 0; c < 4; c++) acc[a][b][c] = 0.f;

    const int lr = tid >> 3, lc = tid & 7;

    auto issue = [&](int kc, int st) {
        const uint32_t s = sb + st * GEMM_STAGE;
        const int kcol = kc * 64;
        #pragma unroll
        for (int it = 0; it < 4; it++) {
            const int r = lr + it * 32;
            const int off = sw128(r, lc);
            const size_t ga = (size_t)(m0 + r) * C_ + kcol + lc * 8;
            cp16(s + off,         Ahi + ga);
            cp16(s + 16384 + off, Alo + ga);
        }
        #pragma unroll
        for (int it = 0; it < 3; it++) {
            const int r = lr + it * 32;
            const int off = sw128(r, lc);
            const size_t gb = (size_t)(n0 + r) * C_ + kcol + lc * 8;
            cp16(s + 32768 + off, Bhi + gb);
            cp16(s + 45056 + off, Blo + gb);
        }
        CP_COMMIT();
    };

    const int a_r = lane & 15, a_co = lane >> 4;
    const int b_r = (lane & 7) + ((lane >> 4) << 3), b_co = (lane >> 3) & 1;
    const int b2_r = lane & 7, b2_co = (lane >> 3) & 1;

    issue(0, 0);
    for (int kc = 0; kc < 12; kc++) {
        CP_WAIT0();
        __syncthreads();
        if (kc + 1 < 12) issue(kc + 1, (kc + 1) & 1);
        const uint32_t s = sb + (kc & 1) * GEMM_STAGE;
        #pragma unroll
        for (int ks = 0; ks < 4; ks++) {
            uint32_t bhi[4], blo[4], bhi2[2], blo2[2];
            {
                const int row = wn + b_r;
                const uint32_t bad = s + 32768 + sw128(row, ks * 2 + b_co);
                ldsm_x4(bhi, bad);
                ldsm_x4(blo, bad + 12288);
                const int row2 = wn + 16 + b2_r;
                const uint32_t bad2 = s + 32768 + sw128(row2, ks * 2 + b2_co);
                ldsm_x2(bhi2, bad2);
                ldsm_x2(blo2, bad2 + 12288);
            }
            uint32_t ahi[4][4], alo[4][4];
            #pragma unroll
            for (int mt = 0; mt < 4; mt++) {
                const int arow = wm + mt * 16 + a_r;
                const uint32_t aad = s + sw128(arow, ks * 2 + a_co);
                ldsm_x4(ahi[mt], aad);
                ldsm_x4(alo[mt], aad + 16384);
            }
            #pragma unroll
            for (int mt = 0; mt < 4; mt++) {
                mma16816(acc[mt][0], ahi[mt], bhi[0], bhi[1]);
                mma16816(acc[mt][1], ahi[mt], bhi[2], bhi[3]);
                mma16816(acc[mt][2], ahi[mt], bhi2[0], bhi2[1]);
            }
            #pragma unroll
            for (int mt = 0; mt < 4; mt++) {
                mma16816(acc[mt][0], ahi[mt], blo[0], blo[1]);
                mma16816(acc[mt][1], ahi[mt], blo[2], blo[3]);
                mma16816(acc[mt][2], ahi[mt], blo2[0], blo2[1]);
            }
            #pragma unroll
            for (int mt = 0; mt < 4; mt++) {
                mma16816(acc[mt][0], alo[mt], bhi[0], bhi[1]);
                mma16816(acc[mt][1], alo[mt], bhi[2], bhi[3]);
                mma16816(acc[mt][2], alo[mt], bhi2[0], bhi2[1]);
            }
        }
        __syncthreads();
    }

    const int er = lane >> 2, ec = (lane & 3) * 2;
    #pragma unroll
    for (int mt = 0; mt < 4; mt++) {
        #pragma unroll
        for (int nt = 0; nt < 3; nt++) {
            const int n = n0 + wn + nt * 8 + ec;
            const float b0 = bias[n], b1 = bias[n + 1];
            #pragma unroll
            for (int half = 0; half < 2; half++) {
                const int m = m0 + wm + mt * 16 + er + half * 8;
                float v0 = acc[mt][nt][half * 2 + 0] + b0;
                float v1 = acc[mt][nt][half * 2 + 1] + b1;
                if (MODE == 1) {
                    *(float2*)(outp + (size_t)m * C_ + n) = make_float2(v0, v1);
                } else {
                    if (z == 0) { v0 *= QSCALE_F; v1 *= QSCALE_F; }  // log2e folded
                    const int bb = m >> 11, t = m & (T_ - 1);
                    const int hh = n >> 6, hs = n & 63;
                    uint32_t hi, lo;
                    split2(v0, v1, hi, lo);
                    __nv_bfloat16* dhi = z ? g_vhi : g_uhi;
                    __nv_bfloat16* dlo = z ? g_vlo : g_ulo;
                    const size_t off = (((size_t)(bb * H_ + hh)) * T_ + t) * HS_ + hs;
                    *(uint32_t*)(dhi + off) = hi;
                    *(uint32_t*)(dlo + off) = lo;
                }
            }
        }
    }
}

// ---------------------------------------------------------------------------
// HMMA flash attention (R14 config — best measured). KV tile 128, occ 1.
// Softmax in exp2 domain (Q pre-scaled by SCALE*log2e).
// PV uses ldsm.x4.trans.
// smem: Qhi@0 Qlo@16K; stage s @ 32K + s*64K: Khi@0 Klo@16K Vhi@32K Vlo@48K
// ---------------------------------------------------------------------------
#define ATTN_SMEM (32768 + 2*65536)

__global__ __launch_bounds__(256, 1)
void attn_mma()
{
    extern __shared__ char sm[];
    const uint32_t sb = smem_u32(sm);
    const int tid = threadIdx.x, wid = tid >> 5, lane = tid & 31;
    const int qt = (int)(gridDim.x - 1) - (int)blockIdx.x;  // longest first
    const int bh = blockIdx.y;
    const int b = bh / H_, h = bh % H_;
    const int q0 = qt * 128;

    const __nv_bfloat16* Kh = g_xhi + (size_t)b * T_ * C_ + h * HS_;
    const __nv_bfloat16* Kl = g_xlo + (size_t)b * T_ * C_ + h * HS_;
    const __nv_bfloat16* Vh = g_vhi + (size_t)bh * T_ * HS_;
    const __nv_bfloat16* Vl = g_vlo + (size_t)bh * T_ * HS_;
    const __nv_bfloat16* Qh = g_uhi + (size_t)bh * T_ * HS_;
    const __nv_bfloat16* Ql = g_ulo + (size_t)bh * T_ * HS_;

    int ldr[4], ldo[4], ldc[4];
    #pragma unroll
    for (int it = 0; it < 4; it++) {
        int f = tid + it * 256;
        int r = f >> 3, ch = f & 7;
        ldr[it] = r; ldc[it] = ch;
        ldo[it] = r * 128 + ((ch ^ (r & 7)) << 4);
    }

    // stage Q
    #pragma unroll
    for (int it = 0; it < 4; it++) {
        const size_t g = (size_t)(q0 + ldr[it]) * HS_ + ldc[it] * 8;
        cp16(sb + ldo[it],         Qh + g);
        cp16(sb + 16384 + ldo[it], Ql + g);
    }
    CP_COMMIT();

    auto issue_kv = [&](int kt, int st) {
        const int k0 = kt * 128;
        const uint32_t s = sb + 32768 + st * 65536;
        #pragma unroll
        for (int it = 0; it < 4; it++) {
            const size_t gk = (size_t)(k0 + ldr[it]) * C_ + ldc[it] * 8;
            const size_t gv = (size_t)(k0 + ldr[it]) * HS_ + ldc[it] * 8;
            cp16(s + ldo[it],         Kh + gk);
            cp16(s + 16384 + ldo[it], Kl + gk);
            cp16(s + 32768 + ldo[it], Vh + gv);
            cp16(s + 49152 + ldo[it], Vl + gv);
        }
        CP_COMMIT();
    };

    issue_kv(0, 0);

    const int a_r = lane & 15, a_co = lane >> 4;
    const int b_r = (lane & 7) + ((lane >> 4) << 3), b_co = (lane >> 3) & 1;

    uint32_t qfh[4][4], qfl[4][4];
    float onn[8][4];
    #pragma unroll
    for (int i = 0; i < 8; i++)
        #pragma unroll
        for (int j = 0; j < 4; j++) onn[i][j] = 0.f;
    float mi0 = -INFINITY, mi1 = -INFINITY, li0 = 0.f, li1 = 0.f;

    for (int kt = 0; kt <= qt; kt++) {
        if (kt + 1 <= qt) { issue_kv(kt + 1, (kt + 1) & 1); CP_WAIT1(); }
        else              { CP_WAIT0(); }
        __syncthreads();

        if (kt == 0) {   // hoist Q fragments once
            const int row = wid * 16 + a_r;
            #pragma unroll
            for (int ks = 0; ks < 4; ks++) {
                const uint32_t ad = sb + row * 128 +
                                    (((ks * 2 + a_co) ^ (row & 7)) << 4);
                ldsm_x4(qfh[ks], ad);
                ldsm_x4(qfl[ks], ad + 16384);
            }
        }

        const uint32_t s0 = sb + 32768 + (kt & 1) * 65536;

        // ---- S = Q @ K^T (pairs of bt; term-grouped passes of 4 MMAs) ----
        float s[16][4];
        #pragma unroll
        for (int i = 0; i < 16; i++)
            #pragma unroll
            for (int j = 0; j < 4; j++) s[i][j] = 0.f;

        #pragma unroll
        for (int ks = 0; ks < 4; ks++) {
            #pragma unroll
            for (int btp = 0; btp < 4; btp++) {
                uint32_t kh[2][4], kl[2][4];
                #pragma unroll
                for (int e = 0; e < 2; e++) {
                    const int row = (btp * 2 + e) * 16 + b_r;
                    const uint32_t ad = s0 + row * 128 +
                                        (((ks * 2 + b_co) ^ (row & 7)) << 4);
                    ldsm_x4(kh[e], ad);
                    ldsm_x4(kl[e], ad + 16384);
                }
                #pragma unroll
                for (int e = 0; e < 2; e++)
                    #pragma unroll
                    for (int hf = 0; hf < 2; hf++)
                        mma16816(s[btp*4 + e*2 + hf], qfh[ks], kh[e][hf*2], kh[e][hf*2+1]);
                #pragma unroll
                for (int e = 0; e < 2; e++)
                    #pragma unroll
                    for (int hf = 0; hf < 2; hf++)
                        mma16816(s[btp*4 + e*2 + hf], qfh[ks], kl[e][hf*2], kl[e][hf*2+1]);
                #pragma unroll
                for (int e = 0; e < 2; e++)
                    #pragma unroll
                    for (int hf = 0; hf < 2; hf++)
                        mma16816(s[btp*4 + e*2 + hf], qfl[ks], kh[e][hf*2], kh[e][hf*2+1]);
            }
        }

        // ---- causal mask (diagonal tile only) ----
        if (kt == qt) {
            const int r0 = wid * 16 + (lane >> 2);
            #pragma unroll
            for (int nt = 0; nt < 16; nt++) {
                const int c = nt * 8 + 2 * (lane & 3);
                if (c     > r0)     s[nt][0] = -INFINITY;
                if (c + 1 > r0)     s[nt][1] = -INFINITY;
                if (c     > r0 + 8) s[nt][2] = -INFINITY;
                if (c + 1 > r0 + 8) s[nt][3] = -INFINITY;
            }
        }

        // ---- online softmax (exp2 domain) ----
        float mx0 = -INFINITY, mx1 = -INFINITY;
        #pragma unroll
        for (int nt = 0; nt < 16; nt++) {
            mx0 = fmaxf(mx0, fmaxf(s[nt][0], s[nt][1]));
            mx1 = fmaxf(mx1, fmaxf(s[nt][2], s[nt][3]));
        }
        mx0 = fmaxf(mx0, __shfl_xor_sync(0xffffffffu, mx0, 1));
        mx0 = fmaxf(mx0, __shfl_xor_sync(0xffffffffu, mx0, 2));
        mx1 = fmaxf(mx1, __shfl_xor_sync(0xffffffffu, mx1, 1));
        mx1 = fmaxf(mx1, __shfl_xor_sync(0xffffffffu, mx1, 2));
        const float mn0 = fmaxf(mi0, mx0), mn1 = fmaxf(mi1, mx1);
        const float al0 = ex2f(mi0 - mn0), al1 = ex2f(mi1 - mn1);
        mi0 = mn0; mi1 = mn1;
        float sum0 = 0.f, sum1 = 0.f;
        #pragma unroll
        for (int nt = 0; nt < 16; nt++) {
            s[nt][0] = ex2f(s[nt][0] - mn0);
            s[nt][1] = ex2f(s[nt][1] - mn0);
            s[nt][2] = ex2f(s[nt][2] - mn1);
            s[nt][3] = ex2f(s[nt][3] - mn1);
            sum0 += s[nt][0] + s[nt][1];
            sum1 += s[nt][2] + s[nt][3];
        }
        sum0 += __shfl_xor_sync(0xffffffffu, sum0, 1);
        sum0 += __shfl_xor_sync(0xffffffffu, sum0, 2);
        sum1 += __shfl_xor_sync(0xffffffffu, sum1, 1);
        sum1 += __shfl_xor_sync(0xffffffffu, sum1, 2);
        li0 = li0 * al0 + sum0;
        li1 = li1 * al1 + sum1;
        #pragma unroll
        for (int i = 0; i < 8; i++) {
            onn[i][0] *= al0; onn[i][1] *= al0;
            onn[i][2] *= al1; onn[i][3] *= al1;
        }

        // ---- O += P @ V (x4-trans V loads; term-grouped passes of 4) ----
        #pragma unroll
        for (int ks2 = 0; ks2 < 8; ks2++) {
            uint32_t ph[4], pl[4];
            split2(s[2*ks2][0],   s[2*ks2][1],   ph[0], pl[0]);
            split2(s[2*ks2][2],   s[2*ks2][3],   ph[1], pl[1]);
            split2(s[2*ks2+1][0], s[2*ks2+1][1], ph[2], pl[2]);
            split2(s[2*ks2+1][2], s[2*ks2+1][3], ph[3], pl[3]);
            const int krow = ks2 * 16 + (lane & 15);
            #pragma unroll
            for (int hb = 0; hb < 2; hb++) {
                uint32_t vh[2][4], vl[2][4];
                #pragma unroll
                for (int pp = 0; pp < 2; pp++) {
                    const int nt2e = hb * 4 + pp * 2;
                    const uint32_t ad = s0 + 32768 + krow * 128 +
                                        (((nt2e + (lane >> 4)) ^ (krow & 7)) << 4);
                    ldsm_x4t(vh[pp], ad);
                    ldsm_x4t(vl[pp], ad + 16384);
                }
                #pragma unroll
                for (int q = 0; q < 4; q++)
                    mma16816(onn[hb*4 + q], ph, vh[q>>1][(q&1)*2], vh[q>>1][(q&1)*2+1]);
                #pragma unroll
                for (int q = 0; q < 4; q++)
                    mma16816(onn[hb*4 + q], ph, vl[q>>1][(q&1)*2], vl[q>>1][(q&1)*2+1]);
                #pragma unroll
                for (int q = 0; q < 4; q++)
                    mma16816(onn[hb*4 + q], pl, vh[q>>1][(q&1)*2], vh[q>>1][(q&1)*2+1]);
            }
        }
        __syncthreads();
    }

    // ---- epilogue: y as bf16 hi/lo ----
    const float inv0 = 1.f / li0, inv1 = 1.f / li1;
    const int r0g = q0 + wid * 16 + (lane >> 2);
    #pragma unroll
    for (int nt2 = 0; nt2 < 8; nt2++) {
        const int c = h * HS_ + nt2 * 8 + 2 * (lane & 3);
        uint32_t hi, lo;
        const size_t o0 = (size_t)(b * T_ + r0g) * C_ + c;
        split2(onn[nt2][0] * inv0, onn[nt2][1] * inv0, hi, lo);
        *(uint32_t*)(g_yhi + o0) = hi;
        *(uint32_t*)(g_ylo + o0) = lo;
        const size_t o1 = (size_t)(b * T_ + r0g + 8) * C_ + c;
        split2(onn[nt2][2] * inv1, onn[nt2][3] * inv1, hi, lo);
        *(uint32_t*)(g_yhi + o1) = hi;
        *(uint32_t*)(g_ylo + o1) = lo;
    }
}

// ---------------------------------------------------------------------------
extern "C" void kernel_launch(void* const* d_in, const int* in_sizes, int n_in,
                              void* d_out, int out_size)
{
    (void)in_sizes; (void)n_in; (void)out_size;
    const float* x      = (const float*)d_in[0];
    const float* w_u_w  = (const float*)d_in[1];
    const float* w_u_b  = (const float*)d_in[2];
    const float* w_v_w  = (const float*)d_in[3];
    const float* w_v_b  = (const float*)d_in[4];
    const float* proj_w = (const float*)d_in[5];
    const float* proj_b = (const float*)d_in[6];
    float* out = (float*)d_out;

    cudaFuncSetAttribute(gemm_pipe<0>,
                         cudaFuncAttributeMaxDynamicSharedMemorySize, GEMM_SMEM_BYTES);
    cudaFuncSetAttribute(gemm_pipe<1>,
                         cudaFuncAttributeMaxDynamicSharedMemorySize, GEMM_SMEM_BYTES);
    cudaFuncSetAttribute(attn_mma,
                         cudaFuncAttributeMaxDynamicSharedMemorySize, ATTN_SMEM);

    split_all<<<592, 256>>>(x, w_u_w, w_v_w, proj_w);

    gemm_pipe<0><<<dim3(8, 32, 2), 256, GEMM_SMEM_BYTES>>>(w_u_b, w_v_b, nullptr);

    attn_mma<<<dim3(T_/128, B_*H_), 256, ATTN_SMEM>>>();

    gemm_pipe<1><<<dim3(8, 32, 1), 256, GEMM_SMEM_BYTES>>>(proj_b, nullptr, out);
}

// round 17
// speedup vs baseline: 1.0334x; 1.0011x over previous
#include <cuda_runtime.h>
#include <cuda_bf16.h>
#include <math.h>
#include <stdint.h>

#define B_   2
#define T_   2048
#define C_   768
#define H_   12
#define HS_  64
#define M_TOT (B_*T_)            // 4096
#define SCALE_F 0.03608439182435161f   // 1/sqrt(768)
// Q pre-scale with log2(e) folded in: softmax runs in exp2 domain.
#define QSCALE_F (0.03608439182435161f * 1.4426950408889634f)

// ---------------- scratch (device globals) ----------------------------------
__device__ __nv_bfloat16 g_xhi[M_TOT*C_], g_xlo[M_TOT*C_];
__device__ __nv_bfloat16 g_yhi[M_TOT*C_], g_ylo[M_TOT*C_];
__device__ __nv_bfloat16 g_uhi[M_TOT*C_], g_ulo[M_TOT*C_];  // scaled Q, [b,h,t,hs]
__device__ __nv_bfloat16 g_vhi[M_TOT*C_], g_vlo[M_TOT*C_];  // V, [b,h,t,hs]
__device__ __nv_bfloat16 g_wuhi[C_*C_], g_wulo[C_*C_];
__device__ __nv_bfloat16 g_wvhi[C_*C_], g_wvlo[C_*C_];
__device__ __nv_bfloat16 g_wphi[C_*C_], g_wplo[C_*C_];

// ---------------------------------------------------------------------------
__device__ __forceinline__ uint32_t smem_u32(const void* p) {
    uint32_t a;
    asm("{ .reg .u64 t; cvta.to.shared.u64 t, %1; cvt.u32.u64 %0, t; }"
        : "=r"(a) : "l"(p));
    return a;
}
__device__ __forceinline__ void ldsm_x4(uint32_t (&r)[4], uint32_t addr) {
    asm volatile("ldmatrix.sync.aligned.m8n8.x4.shared.b16 {%0,%1,%2,%3}, [%4];"
        : "=r"(r[0]), "=r"(r[1]), "=r"(r[2]), "=r"(r[3]) : "r"(addr));
}
__device__ __forceinline__ void ldsm_x4t(uint32_t (&r)[4], uint32_t addr) {
    asm volatile("ldmatrix.sync.aligned.m8n8.x4.trans.shared.b16 {%0,%1,%2,%3}, [%4];"
        : "=r"(r[0]), "=r"(r[1]), "=r"(r[2]), "=r"(r[3]) : "r"(addr));
}
__device__ __forceinline__ void mma16816(float (&d)[4], const uint32_t (&a)[4],
                                         uint32_t b0, uint32_t b1) {
    asm volatile(
        "mma.sync.aligned.m16n8k16.row.col.f32.bf16.bf16.f32 "
        "{%0,%1,%2,%3}, {%4,%5,%6,%7}, {%8,%9}, {%0,%1,%2,%3};"
        : "+f"(d[0]), "+f"(d[1]), "+f"(d[2]), "+f"(d[3])
        : "r"(a[0]), "r"(a[1]), "r"(a[2]), "r"(a[3]), "r"(b0), "r"(b1));
}
__device__ __forceinline__ void cp16(uint32_t dst, const void* src) {
    asm volatile("cp.async.cg.shared.global [%0], [%1], 16;"
                 :: "r"(dst), "l"(src));
}
#define CP_COMMIT() asm volatile("cp.async.commit_group;" ::: "memory")
#define CP_WAIT0()  asm volatile("cp.async.wait_group 0;" ::: "memory")
#define CP_WAIT1()  asm volatile("cp.async.wait_group 1;" ::: "memory")

__device__ __forceinline__ float ex2f(float x) {
    float y;
    asm("ex2.approx.f32 %0, %1;" : "=f"(y) : "f"(x));
    return y;
}

// truncation-based split: hi = top 16 bits (1 PRMT), lo = exact residual
// rounded to bf16 (1 cvt). Dropped lo*lo term ~2^-16 relative.
__device__ __forceinline__ void split2(float f0, float f1, uint32_t& hi, uint32_t& lo) {
    uint32_t u0 = __float_as_uint(f0), u1 = __float_as_uint(f1);
    uint32_t h;
    asm("prmt.b32 %0, %1, %2, 0x7632;" : "=r"(h) : "r"(u0), "r"(u1));
    const float l0 = f0 - __uint_as_float(u0 & 0xffff0000u);
    const float l1 = f1 - __uint_as_float(u1 & 0xffff0000u);
    uint32_t lp;
    asm("cvt.rn.bf16x2.f32 %0, %1, %2;" : "=r"(lp) : "f"(l1), "f"(l0));
    hi = h; lo = lp;
}

// ---------------------------------------------------------------------------
// merged fp32 -> bf16 hi/lo split (grid-stride, one wave)
// ---------------------------------------------------------------------------
#define N4X ((M_TOT*C_)/4)
#define N4W ((C_*C_)/4)
#define NTOT4 (N4X + 3*N4W)

__global__ void split_all(const float* __restrict__ x, const float* __restrict__ wu,
                          const float* __restrict__ wv, const float* __restrict__ wp)
{
    for (int i = blockIdx.x * blockDim.x + threadIdx.x; i < NTOT4;
         i += gridDim.x * blockDim.x) {
        const float* src;
        __nv_bfloat16 *hi, *lo;
        int j;
        if (i < N4X)              { src = x;  hi = g_xhi;  lo = g_xlo;  j = i; }
        else if (i < N4X + N4W)   { src = wu; hi = g_wuhi; lo = g_wulo; j = i - N4X; }
        else if (i < N4X + 2*N4W) { src = wv; hi = g_wvhi; lo = g_wvlo; j = i - N4X - N4W; }
        else                      { src = wp; hi = g_wphi; lo = g_wplo; j = i - N4X - 2*N4W; }
        float4 v = reinterpret_cast<const float4*>(src)[j];
        uint32_t h0, l0, h1, l1;
        split2(v.x, v.y, h0, l0);
        split2(v.z, v.w, h1, l1);
        reinterpret_cast<uint32_t*>(hi)[j*2+0] = h0;
        reinterpret_cast<uint32_t*>(hi)[j*2+1] = h1;
        reinterpret_cast<uint32_t*>(lo)[j*2+0] = l0;
        reinterpret_cast<uint32_t*>(lo)[j*2+1] = l1;
    }
}

// ---------------------------------------------------------------------------
// Pipelined HMMA GEMM. CTA 128x96, warps 4(M)x2(N) -> warp tile 32x48
// (minimizes smem ldsm traffic: 40 tiles/k16 vs 44 for 2x4).
// K-chunk 64, 2 stages, safe 1-ahead pipeline.
// stage (56KB): Ahi@0(16K) Alo@16K Bhi@32K(12K) Blo@45056; sw128.
// MODE 0: fused u/v (blockIdx.z), A = x;  MODE 1: proj, A = y -> fp32 out
// ---------------------------------------------------------------------------
#define GEMM_STAGE   57344
#define GEMM_SMEM_BYTES (2*GEMM_STAGE)

__device__ __forceinline__ int sw128(int r, int c) {
    return r * 128 + ((c ^ (r & 7)) << 4);
}

template<int MODE>
__global__ __launch_bounds__(256, 2)
void gemm_pipe(const float* __restrict__ bias0, const float* __restrict__ bias1,
               float* __restrict__ outp)
{
    extern __shared__ char sm[];
    const uint32_t sb = smem_u32(sm);

    const int z = (MODE == 0) ? blockIdx.z : 0;
    const __nv_bfloat16* Ahi = (MODE == 1) ? g_yhi : g_xhi;
    const __nv_bfloat16* Alo = (MODE == 1) ? g_ylo : g_xlo;
    const __nv_bfloat16* Bhi = (MODE == 1) ? g_wphi : (z ? g_wvhi : g_wuhi);
    const __nv_bfloat16* Blo = (MODE == 1) ? g_wplo : (z ? g_wvlo : g_wulo);
    const float* bias = (MODE == 1) ? bias0 : (z ? bias1 : bias0);

    const int tid = threadIdx.x;
    const int wid = tid >> 5, lane = tid & 31;
    const int m0 = blockIdx.y * 128;
    const int n0 = blockIdx.x * 96;
    const int wm = (wid & 3) * 32;       // 4 warps along M
    const int wn = (wid >> 2) * 48;      // 2 warps along N

    float acc[2][6][4];
    #pragma unroll
    for (int a = 0; a < 2; a++)
        #pragma unroll
        for (int b = 0; b < 6; b++)
            #pragma unroll
            for (int c = 0; c < 4; c++) acc[a][b][c] = 0.f;

    const int lr = tid >> 3, lc = tid & 7;

    auto issue = [&](int kc, int st) {
        const uint32_t s = sb + st * GEMM_STAGE;
        const int kcol = kc * 64;
        #pragma unroll
        for (int it = 0; it < 4; it++) {
            const int r = lr + it * 32;
            const int off = sw128(r, lc);
            const size_t ga = (size_t)(m0 + r) * C_ + kcol + lc * 8;
            cp16(s + off,         Ahi + ga);
            cp16(s + 16384 + off, Alo + ga);
        }
        #pragma unroll
        for (int it = 0; it < 3; it++) {
            const int r = lr + it * 32;
            const int off = sw128(r, lc);
            const size_t gb = (size_t)(n0 + r) * C_ + kcol + lc * 8;
            cp16(s + 32768 + off, Bhi + gb);
            cp16(s + 45056 + off, Blo + gb);
        }
        CP_COMMIT();
    };

    const int a_r = lane & 15, a_co = lane >> 4;
    const int b_r = (lane & 7) + ((lane >> 4) << 3), b_co = (lane >> 3) & 1;

    issue(0, 0);
    for (int kc = 0; kc < 12; kc++) {
        CP_WAIT0();
        __syncthreads();
        if (kc + 1 < 12) issue(kc + 1, (kc + 1) & 1);
        const uint32_t s = sb + (kc & 1) * GEMM_STAGE;
        #pragma unroll
        for (int ks = 0; ks < 4; ks++) {
            // B fragments: 3 x4 groups cover 48 N rows (6 n8 tiles per term)
            uint32_t bhi[3][4], blo[3][4];
            #pragma unroll
            for (int g = 0; g < 3; g++) {
                const int row = wn + g * 16 + b_r;
                const uint32_t bad = s + 32768 + sw128(row, ks * 2 + b_co);
                ldsm_x4(bhi[g], bad);
                ldsm_x4(blo[g], bad + 12288);
            }
            // A fragments: 2 mt tiles of 16 rows
            uint32_t ahi[2][4], alo[2][4];
            #pragma unroll
            for (int mt = 0; mt < 2; mt++) {
                const int arow = wm + mt * 16 + a_r;
                const uint32_t aad = s + sw128(arow, ks * 2 + a_co);
                ldsm_x4(ahi[mt], aad);
                ldsm_x4(alo[mt], aad + 16384);
            }
            // pass 1: hi*hi (12 independent MMAs)
            #pragma unroll
            for (int mt = 0; mt < 2; mt++)
                #pragma unroll
                for (int nt = 0; nt < 6; nt++)
                    mma16816(acc[mt][nt], ahi[mt],
                             bhi[nt >> 1][(nt & 1) * 2], bhi[nt >> 1][(nt & 1) * 2 + 1]);
            // pass 2: hi*lo
            #pragma unroll
            for (int mt = 0; mt < 2; mt++)
                #pragma unroll
                for (int nt = 0; nt < 6; nt++)
                    mma16816(acc[mt][nt], ahi[mt],
                             blo[nt >> 1][(nt & 1) * 2], blo[nt >> 1][(nt & 1) * 2 + 1]);
            // pass 3: lo*hi
            #pragma unroll
            for (int mt = 0; mt < 2; mt++)
                #pragma unroll
                for (int nt = 0; nt < 6; nt++)
                    mma16816(acc[mt][nt], alo[mt],
                             bhi[nt >> 1][(nt & 1) * 2], bhi[nt >> 1][(nt & 1) * 2 + 1]);
        }
        __syncthreads();
    }

    const int er = lane >> 2, ec = (lane & 3) * 2;
    #pragma unroll
    for (int mt = 0; mt < 2; mt++) {
        #pragma unroll
        for (int nt = 0; nt < 6; nt++) {
            const int n = n0 + wn + nt * 8 + ec;
            const float b0 = bias[n], b1 = bias[n + 1];
            #pragma unroll
            for (int half = 0; half < 2; half++) {
                const int m = m0 + wm + mt * 16 + er + half * 8;
                float v0 = acc[mt][nt][half * 2 + 0] + b0;
                float v1 = acc[mt][nt][half * 2 + 1] + b1;
                if (MODE == 1) {
                    *(float2*)(outp + (size_t)m * C_ + n) = make_float2(v0, v1);
                } else {
                    if (z == 0) { v0 *= QSCALE_F; v1 *= QSCALE_F; }  // log2e folded
                    const int bb = m >> 11, t = m & (T_ - 1);
                    const int hh = n >> 6, hs = n & 63;
                    uint32_t hi, lo;
                    split2(v0, v1, hi, lo);
                    __nv_bfloat16* dhi = z ? g_vhi : g_uhi;
                    __nv_bfloat16* dlo = z ? g_vlo : g_ulo;
                    const size_t off = (((size_t)(bb * H_ + hh)) * T_ + t) * HS_ + hs;
                    *(uint32_t*)(dhi + off) = hi;
                    *(uint32_t*)(dlo + off) = lo;
                }
            }
        }
    }
}

// ---------------------------------------------------------------------------
// HMMA flash attention (R14 config — best measured). KV tile 128, occ 1.
// Softmax in exp2 domain (Q pre-scaled by SCALE*log2e).
// PV uses ldsm.x4.trans.
// smem: Qhi@0 Qlo@16K; stage s @ 32K + s*64K: Khi@0 Klo@16K Vhi@32K Vlo@48K
// ---------------------------------------------------------------------------
#define ATTN_SMEM (32768 + 2*65536)

__global__ __launch_bounds__(256, 1)
void attn_mma()
{
    extern __shared__ char sm[];
    const uint32_t sb = smem_u32(sm);
    const int tid = threadIdx.x, wid = tid >> 5, lane = tid & 31;
    const int qt = (int)(gridDim.x - 1) - (int)blockIdx.x;  // longest first
    const int bh = blockIdx.y;
    const int b = bh / H_, h = bh % H_;
    const int q0 = qt * 128;

    const __nv_bfloat16* Kh = g_xhi + (size_t)b * T_ * C_ + h * HS_;
    const __nv_bfloat16* Kl = g_xlo + (size_t)b * T_ * C_ + h * HS_;
    const __nv_bfloat16* Vh = g_vhi + (size_t)bh * T_ * HS_;
    const __nv_bfloat16* Vl = g_vlo + (size_t)bh * T_ * HS_;
    const __nv_bfloat16* Qh = g_uhi + (size_t)bh * T_ * HS_;
    const __nv_bfloat16* Ql = g_ulo + (size_t)bh * T_ * HS_;

    int ldr[4], ldo[4], ldc[4];
    #pragma unroll
    for (int it = 0; it < 4; it++) {
        int f = tid + it * 256;
        int r = f >> 3, ch = f & 7;
        ldr[it] = r; ldc[it] = ch;
        ldo[it] = r * 128 + ((ch ^ (r & 7)) << 4);
    }

    // stage Q
    #pragma unroll
    for (int it = 0; it < 4; it++) {
        const size_t g = (size_t)(q0 + ldr[it]) * HS_ + ldc[it] * 8;
        cp16(sb + ldo[it],         Qh + g);
        cp16(sb + 16384 + ldo[it], Ql + g);
    }
    CP_COMMIT();

    auto issue_kv = [&](int kt, int st) {
        const int k0 = kt * 128;
        const uint32_t s = sb + 32768 + st * 65536;
        #pragma unroll
        for (int it = 0; it < 4; it++) {
            const size_t gk = (size_t)(k0 + ldr[it]) * C_ + ldc[it] * 8;
            const size_t gv = (size_t)(k0 + ldr[it]) * HS_ + ldc[it] * 8;
            cp16(s + ldo[it],         Kh + gk);
            cp16(s + 16384 + ldo[it], Kl + gk);
            cp16(s + 32768 + ldo[it], Vh + gv);
            cp16(s + 49152 + ldo[it], Vl + gv);
        }
        CP_COMMIT();
    };

    issue_kv(0, 0);

    const int a_r = lane & 15, a_co = lane >> 4;
    const int b_r = (lane & 7) + ((lane >> 4) << 3), b_co = (lane >> 3) & 1;

    uint32_t qfh[4][4], qfl[4][4];
    float onn[8][4];
    #pragma unroll
    for (int i = 0; i < 8; i++)
        #pragma unroll
        for (int j = 0; j < 4; j++) onn[i][j] = 0.f;
    float mi0 = -INFINITY, mi1 = -INFINITY, li0 = 0.f, li1 = 0.f;

    for (int kt = 0; kt <= qt; kt++) {
        if (kt + 1 <= qt) { issue_kv(kt + 1, (kt + 1) & 1); CP_WAIT1(); }
        else              { CP_WAIT0(); }
        __syncthreads();

        if (kt == 0) {   // hoist Q fragments once
            const int row = wid * 16 + a_r;
            #pragma unroll
            for (int ks = 0; ks < 4; ks++) {
                const uint32_t ad = sb + row * 128 +
                                    (((ks * 2 + a_co) ^ (row & 7)) << 4);
                ldsm_x4(qfh[ks], ad);
                ldsm_x4(qfl[ks], ad + 16384);
            }
        }

        const uint32_t s0 = sb + 32768 + (kt & 1) * 65536;

        // ---- S = Q @ K^T (pairs of bt; term-grouped passes of 4 MMAs) ----
        float s[16][4];
        #pragma unroll
        for (int i = 0; i < 16; i++)
            #pragma unroll
            for (int j = 0; j < 4; j++) s[i][j] = 0.f;

        #pragma unroll
        for (int ks = 0; ks < 4; ks++) {
            #pragma unroll
            for (int btp = 0; btp < 4; btp++) {
                uint32_t kh[2][4], kl[2][4];
                #pragma unroll
                for (int e = 0; e < 2; e++) {
                    const int row = (btp * 2 + e) * 16 + b_r;
                    const uint32_t ad = s0 + row * 128 +
                                        (((ks * 2 + b_co) ^ (row & 7)) << 4);
                    ldsm_x4(kh[e], ad);
                    ldsm_x4(kl[e], ad + 16384);
                }
                #pragma unroll
                for (int e = 0; e < 2; e++)
                    #pragma unroll
                    for (int hf = 0; hf < 2; hf++)
                        mma16816(s[btp*4 + e*2 + hf], qfh[ks], kh[e][hf*2], kh[e][hf*2+1]);
                #pragma unroll
                for (int e = 0; e < 2; e++)
                    #pragma unroll
                    for (int hf = 0; hf < 2; hf++)
                        mma16816(s[btp*4 + e*2 + hf], qfh[ks], kl[e][hf*2], kl[e][hf*2+1]);
                #pragma unroll
                for (int e = 0; e < 2; e++)
                    #pragma unroll
                    for (int hf = 0; hf < 2; hf++)
                        mma16816(s[btp*4 + e*2 + hf], qfl[ks], kh[e][hf*2], kh[e][hf*2+1]);
            }
        }

        // ---- causal mask (diagonal tile only) ----
        if (kt == qt) {
            const int r0 = wid * 16 + (lane >> 2);
            #pragma unroll
            for (int nt = 0; nt < 16; nt++) {
                const int c = nt * 8 + 2 * (lane & 3);
                if (c     > r0)     s[nt][0] = -INFINITY;
                if (c + 1 > r0)     s[nt][1] = -INFINITY;
                if (c     > r0 + 8) s[nt][2] = -INFINITY;
                if (c + 1 > r0 + 8) s[nt][3] = -INFINITY;
            }
        }

        // ---- online softmax (exp2 domain) ----
        float mx0 = -INFINITY, mx1 = -INFINITY;
        #pragma unroll
        for (int nt = 0; nt < 16; nt++) {
            mx0 = fmaxf(mx0, fmaxf(s[nt][0], s[nt][1]));
            mx1 = fmaxf(mx1, fmaxf(s[nt][2], s[nt][3]));
        }
        mx0 = fmaxf(mx0, __shfl_xor_sync(0xffffffffu, mx0, 1));
        mx0 = fmaxf(mx0, __shfl_xor_sync(0xffffffffu, mx0, 2));
        mx1 = fmaxf(mx1, __shfl_xor_sync(0xffffffffu, mx1, 1));
        mx1 = fmaxf(mx1, __shfl_xor_sync(0xffffffffu, mx1, 2));
        const float mn0 = fmaxf(mi0, mx0), mn1 = fmaxf(mi1, mx1);
        const float al0 = ex2f(mi0 - mn0), al1 = ex2f(mi1 - mn1);
        mi0 = mn0; mi1 = mn1;
        float sum0 = 0.f, sum1 = 0.f;
        #pragma unroll
        for (int nt = 0; nt < 16; nt++) {
            s[nt][0] = ex2f(s[nt][0] - mn0);
            s[nt][1] = ex2f(s[nt][1] - mn0);
            s[nt][2] = ex2f(s[nt][2] - mn1);
            s[nt][3] = ex2f(s[nt][3] - mn1);
            sum0 += s[nt][0] + s[nt][1];
            sum1 += s[nt][2] + s[nt][3];
        }
        sum0 += __shfl_xor_sync(0xffffffffu, sum0, 1);
        sum0 += __shfl_xor_sync(0xffffffffu, sum0, 2);
        sum1 += __shfl_xor_sync(0xffffffffu, sum1, 1);
        sum1 += __shfl_xor_sync(0xffffffffu, sum1, 2);
        li0 = li0 * al0 + sum0;
        li1 = li1 * al1 + sum1;
        #pragma unroll
        for (int i = 0; i < 8; i++) {
            onn[i][0] *= al0; onn[i][1] *= al0;
            onn[i][2] *= al1; onn[i][3] *= al1;
        }

        // ---- O += P @ V (x4-trans V loads; term-grouped passes of 4) ----
        #pragma unroll
        for (int ks2 = 0; ks2 < 8; ks2++) {
            uint32_t ph[4], pl[4];
            split2(s[2*ks2][0],   s[2*ks2][1],   ph[0], pl[0]);
            split2(s[2*ks2][2],   s[2*ks2][3],   ph[1], pl[1]);
            split2(s[2*ks2+1][0], s[2*ks2+1][1], ph[2], pl[2]);
            split2(s[2*ks2+1][2], s[2*ks2+1][3], ph[3], pl[3]);
            const int krow = ks2 * 16 + (lane & 15);
            #pragma unroll
            for (int hb = 0; hb < 2; hb++) {
                uint32_t vh[2][4], vl[2][4];
                #pragma unroll
                for (int pp = 0; pp < 2; pp++) {
                    const int nt2e = hb * 4 + pp * 2;
                    const uint32_t ad = s0 + 32768 + krow * 128 +
                                        (((nt2e + (lane >> 4)) ^ (krow & 7)) << 4);
                    ldsm_x4t(vh[pp], ad);
                    ldsm_x4t(vl[pp], ad + 16384);
                }
                #pragma unroll
                for (int q = 0; q < 4; q++)
                    mma16816(onn[hb*4 + q], ph, vh[q>>1][(q&1)*2], vh[q>>1][(q&1)*2+1]);
                #pragma unroll
                for (int q = 0; q < 4; q++)
                    mma16816(onn[hb*4 + q], ph, vl[q>>1][(q&1)*2], vl[q>>1][(q&1)*2+1]);
                #pragma unroll
                for (int q = 0; q < 4; q++)
                    mma16816(onn[hb*4 + q], pl, vh[q>>1][(q&1)*2], vh[q>>1][(q&1)*2+1]);
            }
        }
        __syncthreads();
    }

    // ---- epilogue: y as bf16 hi/lo ----
    const float inv0 = 1.f / li0, inv1 = 1.f / li1;
    const int r0g = q0 + wid * 16 + (lane >> 2);
    #pragma unroll
    for (int nt2 = 0; nt2 < 8; nt2++) {
        const int c = h * HS_ + nt2 * 8 + 2 * (lane & 3);
        uint32_t hi, lo;
        const size_t o0 = (size_t)(b * T_ + r0g) * C_ + c;
        split2(onn[nt2][0] * inv0, onn[nt2][1] * inv0, hi, lo);
        *(uint32_t*)(g_yhi + o0) = hi;
        *(uint32_t*)(g_ylo + o0) = lo;
        const size_t o1 = (size_t)(b * T_ + r0g + 8) * C_ + c;
        split2(onn[nt2][2] * inv1, onn[nt2][3] * inv1, hi, lo);
        *(uint32_t*)(g_yhi + o1) = hi;
        *(uint32_t*)(g_ylo + o1) = lo;
    }
}

// ---------------------------------------------------------------------------
extern "C" void kernel_launch(void* const* d_in, const int* in_sizes, int n_in,
                              void* d_out, int out_size)
{
    (void)in_sizes; (void)n_in; (void)out_size;
    const float* x      = (const float*)d_in[0];
    const float* w_u_w  = (const float*)d_in[1];
    const float* w_u_b  = (const float*)d_in[2];
    const float* w_v_w  = (const float*)d_in[3];
    const float* w_v_b  = (const float*)d_in[4];
    const float* proj_w = (const float*)d_in[5];
    const float* proj_b = (const float*)d_in[6];
    float* out = (float*)d_out;

    cudaFuncSetAttribute(gemm_pipe<0>,
                         cudaFuncAttributeMaxDynamicSharedMemorySize, GEMM_SMEM_BYTES);
    cudaFuncSetAttribute(gemm_pipe<1>,
                         cudaFuncAttributeMaxDynamicSharedMemorySize, GEMM_SMEM_BYTES);
    cudaFuncSetAttribute(attn_mma,
                         cudaFuncAttributeMaxDynamicSharedMemorySize, ATTN_SMEM);

    split_all<<<592, 256>>>(x, w_u_w, w_v_w, proj_w);

    gemm_pipe<0><<<dim3(8, 32, 2), 256, GEMM_SMEM_BYTES>>>(w_u_b, w_v_b, nullptr);

    attn_mma<<<dim3(T_/128, B_*H_), 256, ATTN_SMEM>>>();

    gemm_pipe<1><<<dim3(8, 32, 1), 256, GEMM_SMEM_BYTES>>>(proj_b, nullptr, out);
}